// round 10
// baseline (speedup 1.0000x reference)
#include <cuda_runtime.h>
#include <cuda_bf16.h>
#include <cuda_fp8.h>
#include <math.h>
#include <stdint.h>
#include <type_traits>

typedef __nv_bfloat16 bf16;

#define Dq 1024
#define Pq 128
#define Bq 4096
#define Nq 8192
#define Cq 1000

// ---------------- scratch (static device memory; no allocations) -----------
__device__ bf16  g_xb [Nq * Dq];
__device__ bf16  g_W1b[Pq * Dq];
__device__ bf16  g_W2b[Pq * Pq];
__device__ bf16  g_W3b[3 * Dq * Pq];
__device__ bf16  g_Wpb[Dq * Dq];
__device__ bf16  g_H1b[Nq * Pq];
__device__ bf16  g_H2b[Nq * Pq];
__device__ bf16  g_Qb [Bq * Dq];
__device__ bf16  g_Kb [Nq * Dq];
__device__ bf16  g_Vb [Nq * Dq];
__device__ bf16  g_Sb [(size_t)Bq * Nq];
__device__ bf16  g_AVb[Bq * Dq];
__device__ float g_F  [Bq * Dq];
__device__ float g_G  [Bq * Dq];
__device__ bf16  g_Ap [(size_t)Bq * 3 * Dq];
__device__ bf16  g_Bp [(size_t)Cq * 3 * Dq];
// fp8 buffers + scale stats
__device__ uint8_t g_Q8 [Bq * Dq];
__device__ uint8_t g_K8 [Nq * Dq];
__device__ uint8_t g_V8t[(size_t)Dq * Nq];
__device__ uint8_t g_S8 [(size_t)Bq * Nq];
__device__ unsigned g_amax[4];
__device__ float    g_dq[4];

// ---------------- helpers ---------------------------------------------------
__device__ __forceinline__ uint32_t s2u(const void* p) {
    uint32_t a;
    asm("{ .reg .u64 t; cvta.to.shared.u64 t, %1; cvt.u32.u64 %0, t; }"
        : "=r"(a) : "l"(p));
    return a;
}
__device__ __forceinline__ void ldmx4(uint32_t* r, uint32_t a) {
    asm volatile("ldmatrix.sync.aligned.m8n8.x4.shared.b16 {%0,%1,%2,%3}, [%4];"
                 : "=r"(r[0]), "=r"(r[1]), "=r"(r[2]), "=r"(r[3]) : "r"(a));
}
__device__ __forceinline__ void ldmx4t(uint32_t* r, uint32_t a) {
    asm volatile("ldmatrix.sync.aligned.m8n8.x4.trans.shared.b16 {%0,%1,%2,%3}, [%4];"
                 : "=r"(r[0]), "=r"(r[1]), "=r"(r[2]), "=r"(r[3]) : "r"(a));
}
__device__ __forceinline__ void mma16816(float* c, const uint32_t* a, const uint32_t* b) {
    asm volatile("mma.sync.aligned.m16n8k16.row.col.f32.bf16.bf16.f32 "
                 "{%0,%1,%2,%3}, {%4,%5,%6,%7}, {%8,%9}, {%0,%1,%2,%3};"
                 : "+f"(c[0]), "+f"(c[1]), "+f"(c[2]), "+f"(c[3])
                 : "r"(a[0]), "r"(a[1]), "r"(a[2]), "r"(a[3]),
                   "r"(b[0]), "r"(b[1]));
}
__device__ __forceinline__ void mma16832(float* c, const uint32_t* a, const uint32_t* b) {
    asm volatile("mma.sync.aligned.m16n8k32.row.col.f32.e4m3.e4m3.f32 "
                 "{%0,%1,%2,%3}, {%4,%5,%6,%7}, {%8,%9}, {%0,%1,%2,%3};"
                 : "+f"(c[0]), "+f"(c[1]), "+f"(c[2]), "+f"(c[3])
                 : "r"(a[0]), "r"(a[1]), "r"(a[2]), "r"(a[3]),
                   "r"(b[0]), "r"(b[1]));
}
__device__ __forceinline__ void cp16(uint32_t dst, const void* src) {
    asm volatile("cp.async.cg.shared.global [%0], [%1], 16;"
                 :: "r"(dst), "l"(src));
}
__device__ __forceinline__ void cp16z(uint32_t dst, const void* src, int sz) {
    asm volatile("cp.async.cg.shared.global [%0], [%1], 16, %2;"
                 :: "r"(dst), "l"(src), "r"(sz));
}
__device__ __forceinline__ void cp_commit() {
    asm volatile("cp.async.commit_group;" ::: "memory");
}
__device__ __forceinline__ unsigned short f2_e4m3x2(float2 f) {
    return __nv_cvt_float2_to_fp8x2(f, __NV_SATFINITE, __NV_E4M3);
}

// ---------------- mma.sync GEMM -----------------------------------
// TRANSB=true : C(MxN) = A(MxK) @ B(NxK)^T ; TRANSB=false: B is (KxN)
// BM=128, BN in {128,256}, 64 bytes of K per stage, 2*BN threads,
// warp tile 64x32, 3-stage cp.async. T in {bf16 (k32/stage), fp8 (k64/stage)}.
#define SROW 80
#define ATILE_B (128 * SROW)           // 10240
#define NSTAGE  3

#define MODE_SMUL   0
#define MODE_BNRELU 1
#define MODE_QKV    2
#define MODE_RESID  3
#define MODE_LS     4

template <int BN, bool TRANSB, typename T>
__device__ __forceinline__ void stage_load(const T* __restrict__ A,
                                           const T* __restrict__ Bm,
                                           int N_, int K_, int m0, int n0, int k0,
                                           uint32_t sbase, int tid)
{
    constexpr int CE = 16 / (int)sizeof(T);   // elems per 16B chunk
    const int Tn = 2 * BN;
#pragma unroll
    for (int i = tid; i < 512; i += Tn) {
        const int row = i >> 2, ch = i & 3;
        cp16(sbase + row * SROW + ch * 16,
             A + (size_t)(m0 + row) * K_ + k0 + ch * CE);
    }
    if (TRANSB) {
#pragma unroll
        for (int i = tid; i < 4 * BN; i += Tn) {
            const int row = i >> 2, ch = i & 3;
            const int grow = n0 + row;
            const int v = (grow < N_);
            cp16z(sbase + ATILE_B + row * SROW + ch * 16,
                  Bm + (size_t)(v ? grow : 0) * K_ + k0 + ch * CE, v ? 16 : 0);
        }
    } else {
        constexpr int CPR = BN / 8;
        constexpr int BROW = 2 * BN + 16;
#pragma unroll
        for (int i = tid; i < 32 * CPR; i += Tn) {
            const int kk = i / CPR, ch = i % CPR;
            cp16(sbase + ATILE_B + kk * BROW + ch * 16,
                 Bm + (size_t)(k0 + kk) * N_ + n0 + ch * CE);
        }
    }
}

template <int BN, bool TRANSB, bool FP8>
__device__ __forceinline__ void compute_stage(uint32_t sbase, int lane,
                                              int wm, int wn,
                                              float acc[4][4][4])
{
    constexpr int BROW = 2 * BN + 16;
    const uint32_t aBase = sbase + (wm * 64 + (lane & 15)) * SROW + (lane >> 4) * 16;
    uint32_t bBase;
    if (TRANSB) {
        bBase = sbase + ATILE_B +
                (wn * 32 + ((lane >> 4) << 3) + (lane & 7)) * SROW +
                (((lane >> 3) & 1) << 4);
    } else {
        bBase = sbase + ATILE_B +
                ((lane & 7) + (((lane >> 3) & 1) << 3)) * BROW +
                (wn * 32 + (lane >> 4) * 8) * 2;
    }
#pragma unroll
    for (int kh = 0; kh < 2; ++kh) {
        uint32_t af[4][4];
#pragma unroll
        for (int tm = 0; tm < 4; ++tm)
            ldmx4(af[tm], aBase + tm * 16 * SROW + kh * 32);
        uint32_t bfr[4][2];
#pragma unroll
        for (int tp = 0; tp < 2; ++tp) {
            uint32_t r[4];
            if (TRANSB) ldmx4(r, bBase + tp * 16 * SROW + kh * 32);
            else        ldmx4t(r, bBase + kh * 16 * BROW + tp * 32);
            bfr[2 * tp][0] = r[0];  bfr[2 * tp][1] = r[1];
            bfr[2 * tp + 1][0] = r[2]; bfr[2 * tp + 1][1] = r[3];
        }
#pragma unroll
        for (int tm = 0; tm < 4; ++tm)
#pragma unroll
            for (int tn = 0; tn < 4; ++tn) {
                if (FP8) mma16832(acc[tm][tn], af[tm], bfr[tn]);
                else     mma16816(acc[tm][tn], af[tm], bfr[tn]);
            }
    }
}

template <int BN, bool TRANSB, bool FP8>
__global__ __launch_bounds__(2 * BN)
void tc_gemm(const void* __restrict__ Av, const void* __restrict__ Bv,
             int M, int N, int K, int mode, float scale,
             const float* __restrict__ dqa, const float* __restrict__ dqb,
             const float* __restrict__ bias, const float* __restrict__ gam,
             const float* __restrict__ bet, const float* __restrict__ mean,
             const float* __restrict__ var, const float* __restrict__ resid,
             const float* __restrict__ lsp,
             void* __restrict__ Cout,
             bf16* __restrict__ qo, bf16* __restrict__ ko, bf16* __restrict__ vo)
{
    using T = typename std::conditional<FP8, uint8_t, bf16>::type;
    const T* A  = (const T*)Av;
    const T* Bm = (const T*)Bv;
    constexpr int NW = BN / 32;
    constexpr int KSTEP = FP8 ? 64 : 32;        // k-elems per stage (64 bytes)
    constexpr int BSTAGE = TRANSB ? BN * SROW : 32 * (2 * BN + 16);
    constexpr int STAGE = ATILE_B + BSTAGE;
    extern __shared__ char smem[];
    const uint32_t sb = s2u(smem);
    const int tid  = threadIdx.x;
    const int lane = tid & 31;
    const int wid  = tid >> 5;
    const int wm = wid / NW, wn = wid % NW;
    const int m0 = blockIdx.y * 128;
    const int n0 = blockIdx.x * BN;
    const int NC = K / KSTEP;

    float acc[4][4][4];
#pragma unroll
    for (int a = 0; a < 4; ++a)
#pragma unroll
        for (int b = 0; b < 4; ++b)
#pragma unroll
            for (int c = 0; c < 4; ++c) acc[a][b][c] = 0.f;

#pragma unroll
    for (int s = 0; s < 2; ++s) {
        stage_load<BN, TRANSB, T>(A, Bm, N, K, m0, n0, s * KSTEP, sb + s * STAGE, tid);
        cp_commit();
    }

    for (int i = 0; i < NC; ++i) {
        asm volatile("cp.async.wait_group 1;" ::: "memory");
        __syncthreads();
        compute_stage<BN, TRANSB, FP8>(sb + (i % NSTAGE) * STAGE, lane, wm, wn, acc);
        if (i + 2 < NC)
            stage_load<BN, TRANSB, T>(A, Bm, N, K, m0, n0, (i + 2) * KSTEP,
                                      sb + ((i + 2) % NSTAGE) * STAGE, tid);
        cp_commit();
    }
    asm volatile("cp.async.wait_group 0;" ::: "memory");

    // ---------------- epilogue ---------------------------------------------
    float sc = scale;
    if (dqa) sc *= *dqa;
    if (dqb) sc *= *dqb;
    const float lsv = (mode == MODE_LS) ? __expf(lsp[0]) : 1.f;

#pragma unroll
    for (int tm = 0; tm < 4; ++tm) {
#pragma unroll
        for (int tn = 0; tn < 4; ++tn) {
            const int r0 = m0 + wm * 64 + tm * 16 + (lane >> 2);
            const int c0 = n0 + wn * 32 + tn * 8 + 2 * (lane & 3);
#pragma unroll
            for (int h = 0; h < 2; ++h) {
                const int row = r0 + 8 * h;
                const float f0 = acc[tm][tn][2 * h];
                const float f1 = acc[tm][tn][2 * h + 1];
                if (mode == MODE_SMUL) {
                    __nv_bfloat162 p = __floats2bfloat162_rn(f0 * sc, f1 * sc);
                    *reinterpret_cast<__nv_bfloat162*>(
                        (bf16*)Cout + (size_t)row * N + c0) = p;
                } else if (mode == MODE_BNRELU) {
                    float x0 = f0 + bias[c0];
                    x0 = (x0 - mean[c0]) * rsqrtf(var[c0] + 1e-5f) * gam[c0] + bet[c0];
                    float x1 = f1 + bias[c0 + 1];
                    x1 = (x1 - mean[c0 + 1]) * rsqrtf(var[c0 + 1] + 1e-5f) * gam[c0 + 1]
                         + bet[c0 + 1];
                    __nv_bfloat162 p = __floats2bfloat162_rn(fmaxf(x0, 0.f),
                                                             fmaxf(x1, 0.f));
                    *reinterpret_cast<__nv_bfloat162*>(
                        (bf16*)Cout + (size_t)row * N + c0) = p;
                } else if (mode == MODE_QKV) {
                    const int g = c0 >> 10;
                    const int d = c0 & 1023;
                    bf16* dst = (g == 0) ? qo : ((g == 1) ? ko : vo);
                    if (dst) {
                        const float hv0 = f0 + bias[3 * d + g];
                        const float hv1 = f1 + bias[3 * (d + 1) + g];
                        __nv_bfloat162 p = __floats2bfloat162_rn(hv0, hv1);
                        *reinterpret_cast<__nv_bfloat162*>(
                            dst + (size_t)row * 1024 + d) = p;
                    }
                } else if (mode == MODE_RESID) {
                    float* Cf = (float*)Cout + (size_t)row * N + c0;
                    const float2 rv = *reinterpret_cast<const float2*>(
                        resid + (size_t)row * N + c0);
                    float2 o;
                    o.x = f0 + bias[c0] + rv.x;
                    o.y = f1 + bias[c0 + 1] + rv.y;
                    *reinterpret_cast<float2*>(Cf) = o;
                } else { // MODE_LS
                    if (c0 < N) {
                        float* Cf = (float*)Cout + (size_t)row * N + c0;
                        Cf[0] = f0 * lsv;
                        Cf[1] = f1 * lsv;
                    }
                }
            }
        }
    }
}

#define SMEM_NT128 (NSTAGE * (ATILE_B + 128 * SROW))           // 61440
#define SMEM_NT256 (NSTAGE * (ATILE_B + 256 * SROW))           // 92160
#define SMEM_NN256 (NSTAGE * (ATILE_B + 32 * (2 * 256 + 16)))  // 81408

// ---------------- small kernels --------------------------------------------
__global__ void f2b_kernel(const float* __restrict__ in, bf16* __restrict__ out, int n)
{
    const int i = (blockIdx.x * blockDim.x + threadIdx.x) * 4;
    if (i < n) {
        const float4 v = *reinterpret_cast<const float4*>(in + i);
        __nv_bfloat162 a = __floats2bfloat162_rn(v.x, v.y);
        __nv_bfloat162 b = __floats2bfloat162_rn(v.z, v.w);
        uint2 pk;
        pk.x = *reinterpret_cast<uint32_t*>(&a);
        pk.y = *reinterpret_cast<uint32_t*>(&b);
        *reinterpret_cast<uint2*>(out + i) = pk;
    }
}

__global__ void f2bW3_kernel(const float* __restrict__ in, bf16* __restrict__ out)
{
    const int idx = blockIdx.x * blockDim.x + threadIdx.x;
    if (idx >= 3072 * 128) return;
    const int rp = idx >> 7, c = idx & 127;
    const int g = rp >> 10, d = rp & 1023;
    out[idx] = __float2bfloat16(in[(3 * d + g) * 128 + c]);
}

// ---- fp8 quantization ------------------------------------------------------
__global__ void zero_amax_kernel(unsigned* a, int i0, int n)
{
    for (int i = 0; i < n; ++i) a[i0 + i] = 0u;
}
__global__ void absmax_bf16_kernel(const bf16* __restrict__ x, int n,
                                   unsigned* __restrict__ amax)
{
    float m = 0.f;
    const int stride = gridDim.x * blockDim.x * 2;
    for (int i = (blockIdx.x * blockDim.x + threadIdx.x) * 2; i < n; i += stride) {
        const float2 f = __bfloat1622float2(
            *reinterpret_cast<const __nv_bfloat162*>(x + i));
        m = fmaxf(m, fmaxf(fabsf(f.x), fabsf(f.y)));
    }
#pragma unroll
    for (int o = 16; o > 0; o >>= 1) m = fmaxf(m, __shfl_xor_sync(0xffffffffu, m, o));
    if ((threadIdx.x & 31) == 0) atomicMax(amax, __float_as_uint(m));
}
__global__ void write_dq_kernel(const unsigned* __restrict__ amax,
                                float* __restrict__ dq)
{
    *dq = __uint_as_float(*amax) / 224.f;
}
// bf16 -> e4m3 with scale 224/amax (k-major copy)
__global__ void cvt_fp8_kernel(const bf16* __restrict__ in, uint8_t* __restrict__ out,
                               int n, const unsigned* __restrict__ amax)
{
    const float qs = 224.f / __uint_as_float(*amax);
    const int i = (blockIdx.x * blockDim.x + threadIdx.x) * 4;
    if (i < n) {
        const uint2 raw = *reinterpret_cast<const uint2*>(in + i);
        float2 a = __bfloat1622float2(*reinterpret_cast<const __nv_bfloat162*>(&raw.x));
        float2 b = __bfloat1622float2(*reinterpret_cast<const __nv_bfloat162*>(&raw.y));
        a.x *= qs; a.y *= qs; b.x *= qs; b.y *= qs;
        const unsigned short lo = f2_e4m3x2(a);
        const unsigned short hi = f2_e4m3x2(b);
        *reinterpret_cast<unsigned*>(out + i) = (unsigned)lo | ((unsigned)hi << 16);
    }
}
// V (Nq x Dq bf16) -> V8t (Dq x Nq e4m3), scaled. Tiles 128(r) x 32(c).
__global__ void cvt_v8t_kernel(const bf16* __restrict__ V, uint8_t* __restrict__ Vt,
                               const unsigned* __restrict__ amax)
{
    __shared__ bf16 sm[128][33];
    const float qs = 224.f / __uint_as_float(*amax);
    const int r0 = blockIdx.x * 128, c0 = blockIdx.y * 32;
    const int tid = threadIdx.x;                 // 256
#pragma unroll
    for (int j = 0; j < 8; ++j) {
        const int idx2 = tid + j * 256;          // 2048 uint loads
        const int c2 = idx2 & 15, r = idx2 >> 4;
        const uint raw = *reinterpret_cast<const uint*>(
            V + (size_t)(r0 + r) * Dq + c0 + c2 * 2);
        sm[r][c2 * 2]     = *reinterpret_cast<const bf16*>(&raw);
        sm[r][c2 * 2 + 1] = *(reinterpret_cast<const bf16*>(&raw) + 1);
    }
    __syncthreads();
    const int tx = tid & 31, ty = tid >> 5;      // tx: 4-col group, ty: row 0..7
#pragma unroll
    for (int j = 0; j < 4; ++j) {
        const int row = ty + j * 8;              // output row within 32 (dim c)
        float2 a, b;
        a.x = __bfloat162float(sm[tx * 4 + 0][row]) * qs;
        a.y = __bfloat162float(sm[tx * 4 + 1][row]) * qs;
        b.x = __bfloat162float(sm[tx * 4 + 2][row]) * qs;
        b.y = __bfloat162float(sm[tx * 4 + 3][row]) * qs;
        const unsigned pk = (unsigned)f2_e4m3x2(a) | ((unsigned)f2_e4m3x2(b) << 16);
        *reinterpret_cast<unsigned*>(
            Vt + (size_t)(c0 + row) * Nq + r0 + tx * 4) = pk;
    }
}

// row softmax over 8192 bf16 cols -> e4m3 out scaled by 256
__global__ void softmax_bf16(const bf16* __restrict__ S, uint8_t* __restrict__ S8)
{
    const bf16* p = S + (size_t)blockIdx.x * 8192;
    uint8_t* q8 = S8 + (size_t)blockIdx.x * 8192;
    const int tid = threadIdx.x;
    const int lane = tid & 31, w = tid >> 5;

    float v[32];
    float mx = -3.4e38f;
#pragma unroll
    for (int i = 0; i < 16; ++i) {
        const __nv_bfloat162 h2 = *reinterpret_cast<const __nv_bfloat162*>(
            p + tid * 2 + (i << 9));
        const float2 f2 = __bfloat1622float2(h2);
        v[2 * i] = f2.x; v[2 * i + 1] = f2.y;
        mx = fmaxf(mx, fmaxf(f2.x, f2.y));
    }
    __shared__ float shm[8], shs[8];
#pragma unroll
    for (int o = 16; o > 0; o >>= 1) mx = fmaxf(mx, __shfl_xor_sync(0xffffffffu, mx, o));
    if (lane == 0) shm[w] = mx;
    __syncthreads();
    if (tid == 0) {
        float m = shm[0];
#pragma unroll
        for (int i = 1; i < 8; ++i) m = fmaxf(m, shm[i]);
        shm[0] = m;
    }
    __syncthreads();
    mx = shm[0];

    float s = 0.f;
#pragma unroll
    for (int i = 0; i < 32; ++i) { v[i] = __expf(v[i] - mx); s += v[i]; }
#pragma unroll
    for (int o = 16; o > 0; o >>= 1) s += __shfl_xor_sync(0xffffffffu, s, o);
    if (lane == 0) shs[w] = s;
    __syncthreads();
    if (tid == 0) {
        float t = 0.f;
#pragma unroll
        for (int i = 0; i < 8; ++i) t += shs[i];
        shs[0] = t;
    }
    __syncthreads();
    const float inv = 256.f / shs[0];
#pragma unroll
    for (int i = 0; i < 16; ++i) {
        float2 f; f.x = v[2 * i] * inv; f.y = v[2 * i + 1] * inv;
        *reinterpret_cast<unsigned short*>(q8 + tid * 2 + (i << 9)) = f2_e4m3x2(f);
    }
}

// row L2-normalize (D=1024) F -> accumulate into G
__global__ void norm_acc_kernel(const float* __restrict__ F, float* __restrict__ G,
                                int accumulate)
{
    const float* p = F + (size_t)blockIdx.x * 1024;
    float* q = G + (size_t)blockIdx.x * 1024;
    const int tid = threadIdx.x;
    const int lane = tid & 31, w = tid >> 5;

    const float4 v = *reinterpret_cast<const float4*>(p + tid * 4);
    float ss = v.x * v.x + v.y * v.y + v.z * v.z + v.w * v.w;
#pragma unroll
    for (int o = 16; o > 0; o >>= 1) ss += __shfl_xor_sync(0xffffffffu, ss, o);
    __shared__ float sh[8];
    if (lane == 0) sh[w] = ss;
    __syncthreads();
    if (tid == 0) {
        float t = 0.f;
#pragma unroll
        for (int i = 0; i < 8; ++i) t += sh[i];
        sh[0] = t;
    }
    __syncthreads();
    const float rn = rsqrtf(sh[0]);

    float4 o;
    if (accumulate) {
        const float4 g0 = *reinterpret_cast<const float4*>(q + tid * 4);
        o = make_float4(g0.x + v.x * rn, g0.y + v.y * rn,
                        g0.z + v.z * rn, g0.w + v.w * rn);
    } else {
        o = make_float4(v.x * rn, v.y * rn, v.z * rn, v.w * rn);
    }
    *reinterpret_cast<float4*>(q + tid * 4) = o;
}

// A' = [Gh | Gh | Gl]  (Bq x 3D)
__global__ void build_Ap_kernel(const float* __restrict__ G, bf16* __restrict__ Ap)
{
    const int idx = blockIdx.x * blockDim.x + threadIdx.x;
    if (idx >= Bq * Dq) return;
    const int r = idx >> 10, c = idx & 1023;
    const float v = G[idx];
    const bf16 h = __float2bfloat16(v);
    const bf16 l = __float2bfloat16(v - __bfloat162float(h));
    bf16* row = Ap + (size_t)r * 3072;
    row[c] = h; row[1024 + c] = h; row[2048 + c] = l;
}

// B' = [Fh | Fl | Fh]  (Cq x 3D)
__global__ void build_Bp_kernel(const float* __restrict__ Ft, bf16* __restrict__ Bp)
{
    const int idx = blockIdx.x * blockDim.x + threadIdx.x;
    if (idx >= Cq * Dq) return;
    const int r = idx >> 10, c = idx & 1023;
    const float v = Ft[idx];
    const bf16 h = __float2bfloat16(v);
    const bf16 l = __float2bfloat16(v - __bfloat162float(h));
    bf16* row = Bp + (size_t)r * 3072;
    row[c] = h; row[1024 + c] = l; row[2048 + c] = h;
}

// ---------------- host side ------------------------------------------------
static void tc(bool transB, const bf16* A, const bf16* B, int M, int N, int K,
               int mode, float scale,
               const float* bias, const float* gam, const float* bet,
               const float* mean, const float* var, const float* resid,
               const float* lsp, void* C, bf16* qo, bf16* ko, bf16* vo)
{
    if (!transB) {
        dim3 grid(N / 256, M / 128);
        tc_gemm<256, false, false><<<grid, 512, SMEM_NN256>>>(A, B, M, N, K, mode,
            scale, nullptr, nullptr, bias, gam, bet, mean, var, resid, lsp, C, qo, ko, vo);
    } else if (N >= 256) {
        dim3 grid((N + 255) / 256, M / 128);
        tc_gemm<256, true, false><<<grid, 512, SMEM_NT256>>>(A, B, M, N, K, mode,
            scale, nullptr, nullptr, bias, gam, bet, mean, var, resid, lsp, C, qo, ko, vo);
    } else {
        dim3 grid((N + 127) / 128, M / 128);
        tc_gemm<128, true, false><<<grid, 256, SMEM_NT128>>>(A, B, M, N, K, mode,
            scale, nullptr, nullptr, bias, gam, bet, mean, var, resid, lsp, C, qo, ko, vo);
    }
}

static void tc8(const uint8_t* A, const uint8_t* B, int M, int N, int K,
                float scale, const float* dqa, const float* dqb, void* C)
{
    dim3 grid(N / 256, M / 128);
    tc_gemm<256, true, true><<<grid, 512, SMEM_NT256>>>(A, B, M, N, K, MODE_SMUL,
        scale, dqa, dqb, nullptr, nullptr, nullptr, nullptr, nullptr, nullptr,
        nullptr, C, nullptr, nullptr, nullptr);
}

static void f2b(const float* in, bf16* out, int n)
{
    f2b_kernel<<<(n / 4 + 255) / 256, 256>>>(in, out, n);
}

extern "C" void kernel_launch(void* const* d_in, const int* in_sizes, int n_in,
                              void* d_out, int out_size)
{
    (void)in_sizes; (void)n_in; (void)out_size;
    const float* Ft  = (const float*)d_in[0];
    const float* Fv  = (const float*)d_in[1];
    const float* Fvs = (const float*)d_in[2];
    const float* Fvt = (const float*)d_in[3];
    const float* W1  = (const float*)d_in[4];
    const float* b1  = (const float*)d_in[5];
    const float* g1  = (const float*)d_in[6];
    const float* be1 = (const float*)d_in[7];
    const float* m1  = (const float*)d_in[8];
    const float* v1  = (const float*)d_in[9];
    const float* W2  = (const float*)d_in[10];
    const float* b2  = (const float*)d_in[11];
    const float* g2  = (const float*)d_in[12];
    const float* be2 = (const float*)d_in[13];
    const float* m2  = (const float*)d_in[14];
    const float* v2  = (const float*)d_in[15];
    const float* W3  = (const float*)d_in[16];
    const float* b3  = (const float*)d_in[17];
    const float* Wp  = (const float*)d_in[18];
    const float* bp  = (const float*)d_in[19];
    const float* ls  = (const float*)d_in[20];
    float* out = (float*)d_out;

    cudaFuncSetAttribute((const void*)tc_gemm<128, true, false>,
                         cudaFuncAttributeMaxDynamicSharedMemorySize, SMEM_NT128);
    cudaFuncSetAttribute((const void*)tc_gemm<256, true, false>,
                         cudaFuncAttributeMaxDynamicSharedMemorySize, SMEM_NT256);
    cudaFuncSetAttribute((const void*)tc_gemm<256, false, false>,
                         cudaFuncAttributeMaxDynamicSharedMemorySize, SMEM_NN256);
    cudaFuncSetAttribute((const void*)tc_gemm<256, true, true>,
                         cudaFuncAttributeMaxDynamicSharedMemorySize, SMEM_NT256);

    bf16 *xb, *W1b, *W2b, *W3b, *Wpb, *H1b, *H2b, *Qb, *Kb, *Vb, *Sb, *AVb, *Ap, *Bp;
    float *F, *G, *dq;
    uint8_t *Q8, *K8, *V8t, *S8;
    unsigned *amax;
    cudaGetSymbolAddress((void**)&xb,  g_xb);
    cudaGetSymbolAddress((void**)&W1b, g_W1b);
    cudaGetSymbolAddress((void**)&W2b, g_W2b);
    cudaGetSymbolAddress((void**)&W3b, g_W3b);
    cudaGetSymbolAddress((void**)&Wpb, g_Wpb);
    cudaGetSymbolAddress((void**)&H1b, g_H1b);
    cudaGetSymbolAddress((void**)&H2b, g_H2b);
    cudaGetSymbolAddress((void**)&Qb,  g_Qb);
    cudaGetSymbolAddress((void**)&Kb,  g_Kb);
    cudaGetSymbolAddress((void**)&Vb,  g_Vb);
    cudaGetSymbolAddress((void**)&Sb,  g_Sb);
    cudaGetSymbolAddress((void**)&AVb, g_AVb);
    cudaGetSymbolAddress((void**)&F,   g_F);
    cudaGetSymbolAddress((void**)&G,   g_G);
    cudaGetSymbolAddress((void**)&Ap,  g_Ap);
    cudaGetSymbolAddress((void**)&Bp,  g_Bp);
    cudaGetSymbolAddress((void**)&Q8,  g_Q8);
    cudaGetSymbolAddress((void**)&K8,  g_K8);
    cudaGetSymbolAddress((void**)&V8t, g_V8t);
    cudaGetSymbolAddress((void**)&S8,  g_S8);
    cudaGetSymbolAddress((void**)&amax, g_amax);
    cudaGetSymbolAddress((void**)&dq,  g_dq);

    // weight conversions (W3 row-permuted for grouped qkv epilogue)
    f2b(W1, W1b, Pq * Dq);
    f2b(W2, W2b, Pq * Pq);
    f2bW3_kernel<<<(3072 * 128 + 255) / 256, 256>>>(W3, W3b);
    f2b(Wp, Wpb, Dq * Dq);

    // ---- pre_project(Fv) -> Q ----
    f2b(Fv, xb, Bq * Dq);
    tc(true, xb,  W1b, Bq, Pq, Dq, MODE_BNRELU, 1.f, b1, g1, be1, m1, v1,
       nullptr, nullptr, H1b, nullptr, nullptr, nullptr);
    tc(true, H1b, W2b, Bq, Pq, Pq, MODE_BNRELU, 1.f, b2, g2, be2, m2, v2,
       nullptr, nullptr, H2b, nullptr, nullptr, nullptr);
    tc(true, H2b, W3b, Bq, 3 * Dq, Pq, MODE_QKV, 1.f, b3, nullptr, nullptr, nullptr,
       nullptr, nullptr, nullptr, nullptr, Qb, nullptr, nullptr);

    // quantize Q once
    zero_amax_kernel<<<1, 1>>>(amax, 0, 1);
    absmax_bf16_kernel<<<256, 256>>>(Qb, Bq * Dq, amax + 0);
    write_dq_kernel<<<1, 1>>>(amax + 0, dq + 0);
    cvt_fp8_kernel<<<(Bq * Dq / 4 + 255) / 256, 256>>>(Qb, Q8, Bq * Dq, amax + 0);

    // ---- per bank ----
    for (int t = 0; t < 2; ++t) {
        const float* bank = t ? Fvt : Fvs;
        f2b(bank, xb, Nq * Dq);
        tc(true, xb,  W1b, Nq, Pq, Dq, MODE_BNRELU, 1.f, b1, g1, be1, m1, v1,
           nullptr, nullptr, H1b, nullptr, nullptr, nullptr);
        tc(true, H1b, W2b, Nq, Pq, Pq, MODE_BNRELU, 1.f, b2, g2, be2, m2, v2,
           nullptr, nullptr, H2b, nullptr, nullptr, nullptr);
        tc(true, H2b, W3b, Nq, 3 * Dq, Pq, MODE_QKV, 1.f, b3, nullptr, nullptr,
           nullptr, nullptr, nullptr, nullptr, nullptr, nullptr, Kb, Vb);

        // quantize K, V (V also transposed to k-major)
        zero_amax_kernel<<<1, 1>>>(amax, 1, 2);
        absmax_bf16_kernel<<<256, 256>>>(Kb, Nq * Dq, amax + 1);
        absmax_bf16_kernel<<<256, 256>>>(Vb, Nq * Dq, amax + 2);
        write_dq_kernel<<<1, 1>>>(amax + 1, dq + 1);
        write_dq_kernel<<<1, 1>>>(amax + 2, dq + 2);
        cvt_fp8_kernel<<<(Nq * Dq / 4 + 255) / 256, 256>>>(Kb, K8, Nq * Dq, amax + 1);
        cvt_v8t_kernel<<<dim3(Nq / 128, Dq / 32), 256>>>(Vb, V8t, amax + 2);

        // S = 0.1 * Q @ K^T   (fp8 -> bf16)
        tc8(Q8, K8, Bq, Nq, Dq, 0.1f, dq + 0, dq + 1, Sb);
        softmax_bf16<<<Bq, 256>>>(Sb, S8);

        // AV = S @ V   (fp8 NT with V^T; S pre-scaled by 256)
        tc8(S8, V8t, Bq, Dq, Nq, 1.f / 256.f, dq + 2, nullptr, AVb);

        // F = Fv + AV @ Wp^T + bp   (fp32)
        tc(true, AVb, Wpb, Bq, Dq, Dq, MODE_RESID, 1.f, bp, nullptr, nullptr,
           nullptr, nullptr, Fv, nullptr, F, nullptr, nullptr, nullptr);

        norm_acc_kernel<<<Bq, 256>>>(F, G, t);
    }

    // ---- logits = exp(ls) * G @ Ft^T via bf16 split (3-term) ----
    build_Ap_kernel<<<(Bq * Dq + 255) / 256, 256>>>(G, Ap);
    build_Bp_kernel<<<(Cq * Dq + 255) / 256, 256>>>(Ft, Bp);
    tc(true, Ap, Bp, Bq, Cq, 3 * Dq, MODE_LS, 1.f, nullptr, nullptr, nullptr,
       nullptr, nullptr, nullptr, ls, out, nullptr, nullptr, nullptr);
}

// round 11
// speedup vs baseline: 1.1257x; 1.1257x over previous
#include <cuda_runtime.h>
#include <cuda_bf16.h>
#include <math.h>
#include <stdint.h>

typedef __nv_bfloat16 bf16;

#define Dq 1024
#define Pq 128
#define Bq 4096
#define Nq 8192
#define Cq 1000
#define Mall 20480              // 4096 + 2*8192

// ---------------- scratch (static device memory; no allocations) -----------
__device__ bf16  g_xb  [(size_t)Mall * Dq];
__device__ bf16  g_W1b [Pq * Dq];
__device__ bf16  g_W2b [Pq * Pq];
__device__ bf16  g_W3b [3 * Dq * Pq];
__device__ bf16  g_Wpb [Dq * Dq];
__device__ bf16  g_H1b [(size_t)Mall * Pq];
__device__ bf16  g_H2b [(size_t)Mall * Pq];
__device__ bf16  g_Qb  [Bq * Dq];
__device__ bf16  g_Kall[(size_t)2 * Nq * Dq];
__device__ bf16  g_Vall[(size_t)2 * Nq * Dq];
__device__ bf16  g_Sall[(size_t)Bq * 2 * Nq];
__device__ bf16  g_AVal[(size_t)2 * Bq * Dq];
__device__ float g_F   [(size_t)2 * Bq * Dq];
__device__ float g_G   [Bq * Dq];
__device__ bf16  g_Ap  [(size_t)Bq * 3 * Dq];
__device__ bf16  g_Bp  [(size_t)Cq * 3 * Dq];

// ---------------- helpers ---------------------------------------------------
__device__ __forceinline__ uint32_t s2u(const void* p) {
    uint32_t a;
    asm("{ .reg .u64 t; cvta.to.shared.u64 t, %1; cvt.u32.u64 %0, t; }"
        : "=r"(a) : "l"(p));
    return a;
}
__device__ __forceinline__ void ldmx4(uint32_t* r, uint32_t a) {
    asm volatile("ldmatrix.sync.aligned.m8n8.x4.shared.b16 {%0,%1,%2,%3}, [%4];"
                 : "=r"(r[0]), "=r"(r[1]), "=r"(r[2]), "=r"(r[3]) : "r"(a));
}
__device__ __forceinline__ void ldmx4t(uint32_t* r, uint32_t a) {
    asm volatile("ldmatrix.sync.aligned.m8n8.x4.trans.shared.b16 {%0,%1,%2,%3}, [%4];"
                 : "=r"(r[0]), "=r"(r[1]), "=r"(r[2]), "=r"(r[3]) : "r"(a));
}
__device__ __forceinline__ void mma16816(float* c, const uint32_t* a, const uint32_t* b) {
    asm volatile("mma.sync.aligned.m16n8k16.row.col.f32.bf16.bf16.f32 "
                 "{%0,%1,%2,%3}, {%4,%5,%6,%7}, {%8,%9}, {%0,%1,%2,%3};"
                 : "+f"(c[0]), "+f"(c[1]), "+f"(c[2]), "+f"(c[3])
                 : "r"(a[0]), "r"(a[1]), "r"(a[2]), "r"(a[3]),
                   "r"(b[0]), "r"(b[1]));
}
__device__ __forceinline__ void cp16(uint32_t dst, const void* src) {
    asm volatile("cp.async.cg.shared.global [%0], [%1], 16;"
                 :: "r"(dst), "l"(src));
}
__device__ __forceinline__ void cp16z(uint32_t dst, const void* src, int sz) {
    asm volatile("cp.async.cg.shared.global [%0], [%1], 16, %2;"
                 :: "r"(dst), "l"(src), "r"(sz));
}
__device__ __forceinline__ void cp_commit() {
    asm volatile("cp.async.commit_group;" ::: "memory");
}

// ---------------- mma.sync GEMM -----------------------------------
// TRANSB=true : C(MxN) = A(MxK) @ B(NxK)^T ; TRANSB=false: B is (KxN)
// BM=128, BN in {128,256}, BK=32, 2*BN threads, warp tile 64x32,
// 3-stage cp.async. A row stride = lda. Optional z-batching via offsets.
#define SROW 80
#define ATILE_B (128 * SROW)           // 10240
#define NSTAGE  3

#define MODE_SMUL   0  // bf16 out = acc*scale
#define MODE_BNRELU 1  // bf16 out = relu(bn(acc+bias))
#define MODE_QKV    2  // row-routed scatter: row<4096 -> q; else k/v at row-4096
#define MODE_RESID  3  // f32 out = acc + bias[c] + resid[row&4095,c]
#define MODE_LS     4  // f32 out = acc * exp(*lsp), ragged-N guarded

template <int BN, bool TRANSB>
__device__ __forceinline__ void stage_load(const bf16* __restrict__ A,
                                           const bf16* __restrict__ Bm,
                                           int N_, int K_, int lda,
                                           int m0, int n0, int k0,
                                           uint32_t sbase, int tid)
{
    const int T = 2 * BN;
#pragma unroll
    for (int i = tid; i < 512; i += T) {
        const int row = i >> 2, ch = i & 3;
        cp16(sbase + row * SROW + ch * 16,
             A + (size_t)(m0 + row) * lda + k0 + ch * 8);
    }
    if (TRANSB) {
#pragma unroll
        for (int i = tid; i < 4 * BN; i += T) {
            const int row = i >> 2, ch = i & 3;
            const int grow = n0 + row;
            const int v = (grow < N_);
            cp16z(sbase + ATILE_B + row * SROW + ch * 16,
                  Bm + (size_t)(v ? grow : 0) * K_ + k0 + ch * 8, v ? 16 : 0);
        }
    } else {
        constexpr int CPR = BN / 8;
        constexpr int BROW = 2 * BN + 16;
#pragma unroll
        for (int i = tid; i < 32 * CPR; i += T) {
            const int kk = i / CPR, ch = i % CPR;
            cp16(sbase + ATILE_B + kk * BROW + ch * 16,
                 Bm + (size_t)(k0 + kk) * N_ + n0 + ch * 8);
        }
    }
}

template <int BN, bool TRANSB>
__device__ __forceinline__ void compute_stage(uint32_t sbase, int lane,
                                              int wm, int wn,
                                              float acc[4][4][4])
{
    constexpr int BROW = 2 * BN + 16;
    const uint32_t aBase = sbase + (wm * 64 + (lane & 15)) * SROW + (lane >> 4) * 16;
    uint32_t bBase;
    if (TRANSB) {
        bBase = sbase + ATILE_B +
                (wn * 32 + ((lane >> 4) << 3) + (lane & 7)) * SROW +
                (((lane >> 3) & 1) << 4);
    } else {
        bBase = sbase + ATILE_B +
                ((lane & 7) + (((lane >> 3) & 1) << 3)) * BROW +
                (wn * 32 + (lane >> 4) * 8) * 2;
    }
#pragma unroll
    for (int kh = 0; kh < 2; ++kh) {
        uint32_t af[4][4];
#pragma unroll
        for (int tm = 0; tm < 4; ++tm)
            ldmx4(af[tm], aBase + tm * 16 * SROW + kh * 32);
        uint32_t bfr[4][2];
#pragma unroll
        for (int tp = 0; tp < 2; ++tp) {
            uint32_t r[4];
            if (TRANSB) ldmx4(r, bBase + tp * 16 * SROW + kh * 32);
            else        ldmx4t(r, bBase + kh * 16 * BROW + tp * 32);
            bfr[2 * tp][0] = r[0];  bfr[2 * tp][1] = r[1];
            bfr[2 * tp + 1][0] = r[2]; bfr[2 * tp + 1][1] = r[3];
        }
#pragma unroll
        for (int tm = 0; tm < 4; ++tm)
#pragma unroll
            for (int tn = 0; tn < 4; ++tn)
                mma16816(acc[tm][tn], af[tm], bfr[tn]);
    }
}

template <int BN, bool TRANSB>
__global__ __launch_bounds__(2 * BN)
void tc_gemm(const bf16* __restrict__ A, const bf16* __restrict__ Bm,
             int M, int N, int K, int lda,
             size_t aOff, size_t bOff, size_t cOffB,
             int mode, float scale,
             const float* __restrict__ bias, const float* __restrict__ gam,
             const float* __restrict__ bet, const float* __restrict__ mean,
             const float* __restrict__ var, const float* __restrict__ resid,
             const float* __restrict__ lsp,
             void* __restrict__ Cout,
             bf16* __restrict__ qo, bf16* __restrict__ ko, bf16* __restrict__ vo)
{
    constexpr int NW = BN / 32;
    constexpr int BSTAGE = TRANSB ? BN * SROW : 32 * (2 * BN + 16);
    constexpr int STAGE = ATILE_B + BSTAGE;
    extern __shared__ char smem[];
    const uint32_t sb = s2u(smem);
    A  += blockIdx.z * aOff;
    Bm += blockIdx.z * bOff;
    Cout = (void*)((char*)Cout + (size_t)blockIdx.z * cOffB);
    const int tid  = threadIdx.x;
    const int lane = tid & 31;
    const int wid  = tid >> 5;
    const int wm = wid / NW, wn = wid % NW;
    const int m0 = blockIdx.y * 128;
    const int n0 = blockIdx.x * BN;
    const int NC = K >> 5;

    float acc[4][4][4];
#pragma unroll
    for (int a = 0; a < 4; ++a)
#pragma unroll
        for (int b = 0; b < 4; ++b)
#pragma unroll
            for (int c = 0; c < 4; ++c) acc[a][b][c] = 0.f;

#pragma unroll
    for (int s = 0; s < 2; ++s) {
        stage_load<BN, TRANSB>(A, Bm, N, K, lda, m0, n0, s * 32, sb + s * STAGE, tid);
        cp_commit();
    }

    for (int i = 0; i < NC; ++i) {
        asm volatile("cp.async.wait_group 1;" ::: "memory");
        __syncthreads();
        compute_stage<BN, TRANSB>(sb + (i % NSTAGE) * STAGE, lane, wm, wn, acc);
        if (i + 2 < NC)
            stage_load<BN, TRANSB>(A, Bm, N, K, lda, m0, n0, (i + 2) * 32,
                                   sb + ((i + 2) % NSTAGE) * STAGE, tid);
        cp_commit();
    }
    asm volatile("cp.async.wait_group 0;" ::: "memory");

    // ---------------- epilogue ---------------------------------------------
    const float lsv = (mode == MODE_LS) ? __expf(lsp[0]) : 1.f;

#pragma unroll
    for (int tm = 0; tm < 4; ++tm) {
#pragma unroll
        for (int tn = 0; tn < 4; ++tn) {
            const int r0 = m0 + wm * 64 + tm * 16 + (lane >> 2);
            const int c0 = n0 + wn * 32 + tn * 8 + 2 * (lane & 3);
#pragma unroll
            for (int h = 0; h < 2; ++h) {
                const int row = r0 + 8 * h;
                const float f0 = acc[tm][tn][2 * h];
                const float f1 = acc[tm][tn][2 * h + 1];
                if (mode == MODE_SMUL) {
                    __nv_bfloat162 p = __floats2bfloat162_rn(f0 * scale, f1 * scale);
                    *reinterpret_cast<__nv_bfloat162*>(
                        (bf16*)Cout + (size_t)row * N + c0) = p;
                } else if (mode == MODE_BNRELU) {
                    float x0 = f0 + bias[c0];
                    x0 = (x0 - mean[c0]) * rsqrtf(var[c0] + 1e-5f) * gam[c0] + bet[c0];
                    float x1 = f1 + bias[c0 + 1];
                    x1 = (x1 - mean[c0 + 1]) * rsqrtf(var[c0 + 1] + 1e-5f) * gam[c0 + 1]
                         + bet[c0 + 1];
                    __nv_bfloat162 p = __floats2bfloat162_rn(fmaxf(x0, 0.f),
                                                             fmaxf(x1, 0.f));
                    *reinterpret_cast<__nv_bfloat162*>(
                        (bf16*)Cout + (size_t)row * N + c0) = p;
                } else if (mode == MODE_QKV) {
                    // cols pre-grouped: g=0 q, g=1 k, g=2 v (W3 rows permuted)
                    const int g = c0 >> 10;
                    const int d = c0 & 1023;
                    const float hv0 = f0 + bias[3 * d + g];
                    const float hv1 = f1 + bias[3 * (d + 1) + g];
                    const __nv_bfloat162 p = __floats2bfloat162_rn(hv0, hv1);
                    if (g == 0) {
                        if (row < Bq)
                            *reinterpret_cast<__nv_bfloat162*>(
                                qo + (size_t)row * 1024 + d) = p;
                    } else if (row >= Bq) {
                        bf16* dst = (g == 1) ? ko : vo;
                        *reinterpret_cast<__nv_bfloat162*>(
                            dst + (size_t)(row - Bq) * 1024 + d) = p;
                    }
                } else if (mode == MODE_RESID) {
                    float* Cf = (float*)Cout + (size_t)row * N + c0;
                    const float2 rv = *reinterpret_cast<const float2*>(
                        resid + (size_t)(row & (Bq - 1)) * N + c0);
                    float2 o;
                    o.x = f0 + bias[c0] + rv.x;
                    o.y = f1 + bias[c0 + 1] + rv.y;
                    *reinterpret_cast<float2*>(Cf) = o;
                } else { // MODE_LS (N ragged; pair guard ok, N even)
                    if (c0 < N) {
                        float* Cf = (float*)Cout + (size_t)row * N + c0;
                        Cf[0] = f0 * lsv;
                        Cf[1] = f1 * lsv;
                    }
                }
            }
        }
    }
}

#define SMEM_NT128 (NSTAGE * (ATILE_B + 128 * SROW))           // 61440
#define SMEM_NT256 (NSTAGE * (ATILE_B + 256 * SROW))           // 92160
#define SMEM_NN256 (NSTAGE * (ATILE_B + 32 * (2 * 256 + 16)))  // 81408

// ---------------- small kernels --------------------------------------------
__global__ void f2b_kernel(const float* __restrict__ in, bf16* __restrict__ out, int n)
{
    const int i = (blockIdx.x * blockDim.x + threadIdx.x) * 4;
    if (i < n) {
        const float4 v = *reinterpret_cast<const float4*>(in + i);
        __nv_bfloat162 a = __floats2bfloat162_rn(v.x, v.y);
        __nv_bfloat162 b = __floats2bfloat162_rn(v.z, v.w);
        uint2 pk;
        pk.x = *reinterpret_cast<uint32_t*>(&a);
        pk.y = *reinterpret_cast<uint32_t*>(&b);
        *reinterpret_cast<uint2*>(out + i) = pk;
    }
}

// W3 (3072,128) -> bf16 with rows permuted: out row g*1024+d = orig row 3d+g
__global__ void f2bW3_kernel(const float* __restrict__ in, bf16* __restrict__ out)
{
    const int idx = blockIdx.x * blockDim.x + threadIdx.x;
    if (idx >= 3072 * 128) return;
    const int rp = idx >> 7, c = idx & 127;
    const int g = rp >> 10, d = rp & 1023;
    out[idx] = __float2bfloat16(in[(3 * d + g) * 128 + c]);
}

// in-place row softmax over 8192 bf16 cols; rows have stride 16384,
// blockIdx.y selects bank half.
__global__ void softmax_bf16(bf16* __restrict__ S)
{
    bf16* p = S + (size_t)blockIdx.x * 16384 + (size_t)blockIdx.y * 8192;
    const int tid = threadIdx.x;
    const int lane = tid & 31, w = tid >> 5;

    float v[32];
    float mx = -3.4e38f;
#pragma unroll
    for (int i = 0; i < 16; ++i) {
        const __nv_bfloat162 h2 = *reinterpret_cast<const __nv_bfloat162*>(
            p + tid * 2 + (i << 9));
        const float2 f2 = __bfloat1622float2(h2);
        v[2 * i] = f2.x; v[2 * i + 1] = f2.y;
        mx = fmaxf(mx, fmaxf(f2.x, f2.y));
    }
    __shared__ float shm[8], shs[8];
#pragma unroll
    for (int o = 16; o > 0; o >>= 1) mx = fmaxf(mx, __shfl_xor_sync(0xffffffffu, mx, o));
    if (lane == 0) shm[w] = mx;
    __syncthreads();
    if (tid == 0) {
        float m = shm[0];
#pragma unroll
        for (int i = 1; i < 8; ++i) m = fmaxf(m, shm[i]);
        shm[0] = m;
    }
    __syncthreads();
    mx = shm[0];

    float s = 0.f;
#pragma unroll
    for (int i = 0; i < 32; ++i) { v[i] = __expf(v[i] - mx); s += v[i]; }
#pragma unroll
    for (int o = 16; o > 0; o >>= 1) s += __shfl_xor_sync(0xffffffffu, s, o);
    if (lane == 0) shs[w] = s;
    __syncthreads();
    if (tid == 0) {
        float t = 0.f;
#pragma unroll
        for (int i = 0; i < 8; ++i) t += shs[i];
        shs[0] = t;
    }
    __syncthreads();
    const float inv = 1.f / shs[0];
#pragma unroll
    for (int i = 0; i < 16; ++i) {
        const __nv_bfloat162 h2 = __floats2bfloat162_rn(v[2 * i] * inv,
                                                        v[2 * i + 1] * inv);
        *reinterpret_cast<__nv_bfloat162*>(p + tid * 2 + (i << 9)) = h2;
    }
}

// G[r] = F[r]/||F[r]|| + F[r+4096]/||F[r+4096]||  (both banks in one pass)
__global__ void norm2_acc_kernel(const float* __restrict__ F, float* __restrict__ G)
{
    const float* p0 = F + (size_t)blockIdx.x * 1024;
    const float* p1 = p0 + (size_t)Bq * 1024;
    float* q = G + (size_t)blockIdx.x * 1024;
    const int tid = threadIdx.x;
    const int lane = tid & 31, w = tid >> 5;

    const float4 v0 = *reinterpret_cast<const float4*>(p0 + tid * 4);
    const float4 v1 = *reinterpret_cast<const float4*>(p1 + tid * 4);
    float s0 = v0.x * v0.x + v0.y * v0.y + v0.z * v0.z + v0.w * v0.w;
    float s1 = v1.x * v1.x + v1.y * v1.y + v1.z * v1.z + v1.w * v1.w;
#pragma unroll
    for (int o = 16; o > 0; o >>= 1) {
        s0 += __shfl_xor_sync(0xffffffffu, s0, o);
        s1 += __shfl_xor_sync(0xffffffffu, s1, o);
    }
    __shared__ float sh0[8], sh1[8];
    if (lane == 0) { sh0[w] = s0; sh1[w] = s1; }
    __syncthreads();
    if (tid == 0) {
        float t0 = 0.f, t1 = 0.f;
#pragma unroll
        for (int i = 0; i < 8; ++i) { t0 += sh0[i]; t1 += sh1[i]; }
        sh0[0] = t0; sh1[0] = t1;
    }
    __syncthreads();
    const float rn0 = rsqrtf(sh0[0]);
    const float rn1 = rsqrtf(sh1[0]);

    float4 o;
    o.x = v0.x * rn0 + v1.x * rn1;
    o.y = v0.y * rn0 + v1.y * rn1;
    o.z = v0.z * rn0 + v1.z * rn1;
    o.w = v0.w * rn0 + v1.w * rn1;
    *reinterpret_cast<float4*>(q + tid * 4) = o;
}

// A' = [Gh | Gh | Gl]  (Bq x 3D)
__global__ void build_Ap_kernel(const float* __restrict__ G, bf16* __restrict__ Ap)
{
    const int idx = blockIdx.x * blockDim.x + threadIdx.x;
    if (idx >= Bq * Dq) return;
    const int r = idx >> 10, c = idx & 1023;
    const float v = G[idx];
    const bf16 h = __float2bfloat16(v);
    const bf16 l = __float2bfloat16(v - __bfloat162float(h));
    bf16* row = Ap + (size_t)r * 3072;
    row[c] = h; row[1024 + c] = h; row[2048 + c] = l;
}

// B' = [Fh | Fl | Fh]  (Cq x 3D)
__global__ void build_Bp_kernel(const float* __restrict__ Ft, bf16* __restrict__ Bp)
{
    const int idx = blockIdx.x * blockDim.x + threadIdx.x;
    if (idx >= Cq * Dq) return;
    const int r = idx >> 10, c = idx & 1023;
    const float v = Ft[idx];
    const bf16 h = __float2bfloat16(v);
    const bf16 l = __float2bfloat16(v - __bfloat162float(h));
    bf16* row = Bp + (size_t)r * 3072;
    row[c] = h; row[1024 + c] = l; row[2048 + c] = h;
}

// ---------------- host side ------------------------------------------------
struct GemmArgs {
    const float *bias = nullptr, *gam = nullptr, *bet = nullptr;
    const float *mean = nullptr, *var = nullptr, *resid = nullptr, *lsp = nullptr;
    bf16 *qo = nullptr, *ko = nullptr, *vo = nullptr;
    int lda = 0;                 // 0 -> K
    size_t aOff = 0, bOff = 0, cOffB = 0;
    int gz = 1;
};

static void tc(bool transB, const bf16* A, const bf16* B, int M, int N, int K,
               int mode, float scale, void* C, const GemmArgs& g)
{
    const int lda = g.lda ? g.lda : K;
    if (!transB) {
        dim3 grid(N / 256, M / 128, g.gz);
        tc_gemm<256, false><<<grid, 512, SMEM_NN256>>>(A, B, M, N, K, lda,
            g.aOff, g.bOff, g.cOffB, mode, scale, g.bias, g.gam, g.bet,
            g.mean, g.var, g.resid, g.lsp, C, g.qo, g.ko, g.vo);
    } else if (N >= 256) {
        dim3 grid((N + 255) / 256, M / 128, g.gz);
        tc_gemm<256, true><<<grid, 512, SMEM_NT256>>>(A, B, M, N, K, lda,
            g.aOff, g.bOff, g.cOffB, mode, scale, g.bias, g.gam, g.bet,
            g.mean, g.var, g.resid, g.lsp, C, g.qo, g.ko, g.vo);
    } else {
        dim3 grid((N + 127) / 128, M / 128, g.gz);
        tc_gemm<128, true><<<grid, 256, SMEM_NT128>>>(A, B, M, N, K, lda,
            g.aOff, g.bOff, g.cOffB, mode, scale, g.bias, g.gam, g.bet,
            g.mean, g.var, g.resid, g.lsp, C, g.qo, g.ko, g.vo);
    }
}

static void f2b(const float* in, bf16* out, int n)
{
    f2b_kernel<<<(n / 4 + 255) / 256, 256>>>(in, out, n);
}

extern "C" void kernel_launch(void* const* d_in, const int* in_sizes, int n_in,
                              void* d_out, int out_size)
{
    (void)in_sizes; (void)n_in; (void)out_size;
    const float* Ft  = (const float*)d_in[0];
    const float* Fv  = (const float*)d_in[1];
    const float* Fvs = (const float*)d_in[2];
    const float* Fvt = (const float*)d_in[3];
    const float* W1  = (const float*)d_in[4];
    const float* b1  = (const float*)d_in[5];
    const float* g1  = (const float*)d_in[6];
    const float* be1 = (const float*)d_in[7];
    const float* m1  = (const float*)d_in[8];
    const float* v1  = (const float*)d_in[9];
    const float* W2  = (const float*)d_in[10];
    const float* b2  = (const float*)d_in[11];
    const float* g2  = (const float*)d_in[12];
    const float* be2 = (const float*)d_in[13];
    const float* m2  = (const float*)d_in[14];
    const float* v2  = (const float*)d_in[15];
    const float* W3  = (const float*)d_in[16];
    const float* b3  = (const float*)d_in[17];
    const float* Wp  = (const float*)d_in[18];
    const float* bp  = (const float*)d_in[19];
    const float* ls  = (const float*)d_in[20];
    float* out = (float*)d_out;

    cudaFuncSetAttribute((const void*)tc_gemm<128, true>,
                         cudaFuncAttributeMaxDynamicSharedMemorySize, SMEM_NT128);
    cudaFuncSetAttribute((const void*)tc_gemm<256, true>,
                         cudaFuncAttributeMaxDynamicSharedMemorySize, SMEM_NT256);
    cudaFuncSetAttribute((const void*)tc_gemm<256, false>,
                         cudaFuncAttributeMaxDynamicSharedMemorySize, SMEM_NN256);

    bf16 *xb, *W1b, *W2b, *W3b, *Wpb, *H1b, *H2b, *Qb, *Kall, *Vall, *Sall, *AVal, *Ap, *Bp;
    float *F, *G;
    cudaGetSymbolAddress((void**)&xb,   g_xb);
    cudaGetSymbolAddress((void**)&W1b,  g_W1b);
    cudaGetSymbolAddress((void**)&W2b,  g_W2b);
    cudaGetSymbolAddress((void**)&W3b,  g_W3b);
    cudaGetSymbolAddress((void**)&Wpb,  g_Wpb);
    cudaGetSymbolAddress((void**)&H1b,  g_H1b);
    cudaGetSymbolAddress((void**)&H2b,  g_H2b);
    cudaGetSymbolAddress((void**)&Qb,   g_Qb);
    cudaGetSymbolAddress((void**)&Kall, g_Kall);
    cudaGetSymbolAddress((void**)&Vall, g_Vall);
    cudaGetSymbolAddress((void**)&Sall, g_Sall);
    cudaGetSymbolAddress((void**)&AVal, g_AVal);
    cudaGetSymbolAddress((void**)&F,    g_F);
    cudaGetSymbolAddress((void**)&G,    g_G);
    cudaGetSymbolAddress((void**)&Ap,   g_Ap);
    cudaGetSymbolAddress((void**)&Bp,   g_Bp);

    // weight conversions (W3 row-permuted for grouped qkv epilogue)
    f2b(W1, W1b, Pq * Dq);
    f2b(W2, W2b, Pq * Pq);
    f2bW3_kernel<<<(3072 * 128 + 255) / 256, 256>>>(W3, W3b);
    f2b(Wp, Wpb, Dq * Dq);

    // ---- batched pre_project: rows = [Fv(4096); Fvs(8192); Fvt(8192)] ----
    f2b(Fv,  xb,                     Bq * Dq);
    f2b(Fvs, xb + (size_t)Bq * Dq,   Nq * Dq);
    f2b(Fvt, xb + (size_t)(Bq + Nq) * Dq, Nq * Dq);

    {
        GemmArgs a; a.bias = b1; a.gam = g1; a.bet = be1; a.mean = m1; a.var = v1;
        tc(true, xb, W1b, Mall, Pq, Dq, MODE_BNRELU, 1.f, H1b, a);
    }
    {
        GemmArgs a; a.bias = b2; a.gam = g2; a.bet = be2; a.mean = m2; a.var = v2;
        tc(true, H1b, W2b, Mall, Pq, Pq, MODE_BNRELU, 1.f, H2b, a);
    }
    {
        GemmArgs a; a.bias = b3; a.qo = Qb; a.ko = Kall; a.vo = Vall;
        tc(true, H2b, W3b, Mall, 3 * Dq, Pq, MODE_QKV, 1.f, nullptr, a);
    }

    // ---- S_all = 0.1 * Q @ [K0;K1]^T  (4096 x 16384, bf16) ----
    {
        GemmArgs a;
        tc(true, Qb, Kall, Bq, 2 * Nq, Dq, MODE_SMUL, 0.1f, Sall, a);
    }
    softmax_bf16<<<dim3(Bq, 2), 256>>>(Sall);

    // ---- AV_z = S_z @ V_z  (z-batched NN GEMM) ----
    {
        GemmArgs a;
        a.lda = 2 * Nq;                     // S row stride
        a.aOff = (size_t)Nq;                // bank column offset within S row
        a.bOff = (size_t)Nq * Dq;           // V bank offset
        a.cOffB = (size_t)Bq * Dq * sizeof(bf16);
        a.gz = 2;
        tc(false, Sall, Vall, Bq, Dq, Nq, MODE_SMUL, 1.f, AVal, a);
    }

    // ---- F = Fv + AV @ Wp^T + bp  (both banks, M=8192, fp32) ----
    {
        GemmArgs a; a.bias = bp; a.resid = Fv;
        tc(true, AVal, Wpb, 2 * Bq, Dq, Dq, MODE_RESID, 1.f, F, a);
    }

    // ---- G = sum of normalized banks ----
    norm2_acc_kernel<<<Bq, 256>>>(F, G);

    // ---- logits = exp(ls) * G @ Ft^T via bf16 split (3-term) ----
    build_Ap_kernel<<<(Bq * Dq + 255) / 256, 256>>>(G, Ap);
    build_Bp_kernel<<<(Cq * Dq + 255) / 256, 256>>>(Ft, Bp);
    {
        GemmArgs a; a.lsp = ls;
        tc(true, Ap, Bp, Bq, Cq, 3 * Dq, MODE_LS, 1.f, out, a);
    }
}